// round 11
// baseline (speedup 1.0000x reference)
#include <cuda_runtime.h>
#include <cuda_bf16.h>
#include <math.h>
#include <stdint.h>

#define BATCH 4
#define T_SEQ 1024
#define EMB   1024
#define NH    16
#define HD    64
#define HID   1024
#define NROWS (BATCH * T_SEQ)   // 4096
#define NDIAG 257
#define NDIAGP 260              // padded stride (float4-aligned rows)

// ---------------- scratch ----------------
__device__ float g_q[NROWS * HID];
__device__ float g_k[NROWS * HID];
__device__ float g_v[NROWS * HID];
__device__ float g_att[NROWS * HID];
__device__ float g_R[NDIAG * HD];
__device__ float g_relv[(size_t)BATCH * NH * T_SEQ * NDIAGP];
// bf16-split operands
__device__ __nv_bfloat16 g_A_hi[NROWS * HID];
__device__ __nv_bfloat16 g_A_lo[NROWS * HID];
__device__ __nv_bfloat16 g_WT_hi[4 * HID * EMB];   // W^T slots: 0=q 1=k 2=v 3=o
__device__ __nv_bfloat16 g_WT_lo[4 * HID * EMB];

// ================= helpers =================
__device__ __forceinline__ uint32_t smem_u32(const void* p) {
    uint32_t a;
    asm("{ .reg .u64 t; cvta.to.shared.u64 t, %1; cvt.u32.u64 %0, t; }"
        : "=r"(a) : "l"(p));
    return a;
}
__device__ __forceinline__ uint32_t lds32(uint32_t a) {
    uint32_t v;
    asm("ld.shared.b32 %0, [%1];" : "=r"(v) : "r"(a));
    return v;
}
__device__ __forceinline__ void cp16(uint32_t s, const void* g) {
    asm volatile("cp.async.cg.shared.global [%0], [%1], 16;"
                 :: "r"(s), "l"(g) : "memory");
}
#define CP_COMMIT() asm volatile("cp.async.commit_group;" ::: "memory")
#define CP_WAIT1()  asm volatile("cp.async.wait_group 1;" ::: "memory")
#define CP_WAIT0()  asm volatile("cp.async.wait_group 0;" ::: "memory")

#define MMA16816(d, a, b) \
    asm volatile("mma.sync.aligned.m16n8k16.row.col.f32.bf16.bf16.f32 " \
        "{%0,%1,%2,%3}, {%4,%5,%6,%7}, {%8,%9}, {%0,%1,%2,%3};" \
        : "+f"((d)[0]), "+f"((d)[1]), "+f"((d)[2]), "+f"((d)[3]) \
        : "r"((a)[0]), "r"((a)[1]), "r"((a)[2]), "r"((a)[3]), \
          "r"((b)[0]), "r"((b)[1]))

// ================= split prep kernels (fp32 -> bf16 hi/lo) =================
__global__ void __launch_bounds__(256)
split_kernel(const float* __restrict__ A, __nv_bfloat16* __restrict__ hi,
             __nv_bfloat16* __restrict__ lo)
{
    size_t i = ((size_t)blockIdx.x * 256 + threadIdx.x) * 4;
    float4 v = *(const float4*)(A + i);
    __nv_bfloat16 h0 = __float2bfloat16(v.x);
    __nv_bfloat16 h1 = __float2bfloat16(v.y);
    __nv_bfloat16 h2 = __float2bfloat16(v.z);
    __nv_bfloat16 h3 = __float2bfloat16(v.w);
    __nv_bfloat162 hp0; hp0.x = h0; hp0.y = h1;
    __nv_bfloat162 hp1; hp1.x = h2; hp1.y = h3;
    __nv_bfloat162 lp0, lp1;
    lp0.x = __float2bfloat16(v.x - __bfloat162float(h0));
    lp0.y = __float2bfloat16(v.y - __bfloat162float(h1));
    lp1.x = __float2bfloat16(v.z - __bfloat162float(h2));
    lp1.y = __float2bfloat16(v.w - __bfloat162float(h3));
    *(__nv_bfloat162*)(hi + i)     = hp0;
    *(__nv_bfloat162*)(hi + i + 2) = hp1;
    *(__nv_bfloat162*)(lo + i)     = lp0;
    *(__nv_bfloat162*)(lo + i + 2) = lp1;
}

// out[n][k] = W[k][n], split hi/lo bf16.  slot = blockIdx.z selects src/dst.
__global__ void __launch_bounds__(256)
trans_split_qkv_kernel(const float* __restrict__ Wq, const float* __restrict__ Wk,
                       const float* __restrict__ Wv,
                       __nv_bfloat16* __restrict__ oh, __nv_bfloat16* __restrict__ ol)
{
    __shared__ float tile[32][33];
    int slot = blockIdx.z;
    const float* W = (slot == 0) ? Wq : (slot == 1) ? Wk : Wv;
    size_t dofs = (size_t)slot * HID * EMB;
    int n0 = blockIdx.x * 32, k0 = blockIdx.y * 32;
    int tx = threadIdx.x & 31, ty = threadIdx.x >> 5;  // 32 x 8
    #pragma unroll
    for (int r = ty; r < 32; r += 8)
        tile[r][tx] = W[(size_t)(k0 + r) * HID + n0 + tx];
    __syncthreads();
    #pragma unroll
    for (int r = ty; r < 32; r += 8) {
        float v = tile[tx][r];             // W[k0+tx][n0+r]
        __nv_bfloat16 h = __float2bfloat16(v);
        oh[dofs + (size_t)(n0 + r) * EMB + k0 + tx] = h;
        ol[dofs + (size_t)(n0 + r) * EMB + k0 + tx] =
            __float2bfloat16(v - __bfloat162float(h));
    }
}

__global__ void __launch_bounds__(256)
trans_split_kernel(const float* __restrict__ W, __nv_bfloat16* __restrict__ oh,
                   __nv_bfloat16* __restrict__ ol)
{
    __shared__ float tile[32][33];
    int n0 = blockIdx.x * 32, k0 = blockIdx.y * 32;
    int tx = threadIdx.x & 31, ty = threadIdx.x >> 5;
    #pragma unroll
    for (int r = ty; r < 32; r += 8)
        tile[r][tx] = W[(size_t)(k0 + r) * HID + n0 + tx];
    __syncthreads();
    #pragma unroll
    for (int r = ty; r < 32; r += 8) {
        float v = tile[tx][r];
        __nv_bfloat16 h = __float2bfloat16(v);
        oh[(size_t)(n0 + r) * EMB + k0 + tx] = h;
        ol[(size_t)(n0 + r) * EMB + k0 + tx] =
            __float2bfloat16(v - __bfloat162float(h));
    }
}

// ================= bf16x3 mma.sync GEMM (occ=2, term-major issue) =================
#define MT 128
#define NT 128
#define KT 32
#define NKT (EMB / KT)      // 32
#define ROWB 80
#define ARR_B (128 * ROWB)
#define STAGE_B (4 * ARR_B)
#define DYN_SMEM_GEMM (2 * STAGE_B)   // 81920

extern __shared__ char dynsmem[];

__device__ __forceinline__ void issue_stage(
    uint32_t stage, int kt, int m0, int n0, int t,
    const __nv_bfloat16* __restrict__ Ah, const __nv_bfloat16* __restrict__ Al,
    const __nv_bfloat16* __restrict__ Bh, const __nv_bfloat16* __restrict__ Bl)
{
    const __nv_bfloat16* gp[4] = {Ah, Al, Bh, Bl};
    #pragma unroll
    for (int arr = 0; arr < 4; ++arr) {
        int rbase = (arr < 2) ? m0 : n0;
        uint32_t soff = stage + arr * ARR_B;
        #pragma unroll
        for (int q = 0; q < 2; ++q) {
            int c = t + q * 256;
            int row = c >> 2, seg = c & 3;
            const char* src = (const char*)(gp[arr] + (size_t)(rbase + row) * EMB + kt * KT)
                              + seg * 16;
            cp16(soff + row * ROWB + seg * 16, src);
        }
    }
}

// blockIdx.z selects weight slot + output target (C0/C1/C2).
__global__ void __launch_bounds__(256, 2)
gemm_bf16x3_kernel(const __nv_bfloat16* __restrict__ Ah, const __nv_bfloat16* __restrict__ Al,
                   const __nv_bfloat16* __restrict__ BhBase, const __nv_bfloat16* __restrict__ BlBase,
                   const float* __restrict__ bias,
                   float* __restrict__ C0, float* __restrict__ C1, float* __restrict__ C2)
{
    int slot = blockIdx.z;
    const __nv_bfloat16* Bh = BhBase + (size_t)slot * HID * EMB;
    const __nv_bfloat16* Bl = BlBase + (size_t)slot * HID * EMB;
    float* C = (slot == 0) ? C0 : (slot == 1) ? C1 : C2;

    uint32_t sb = smem_u32(dynsmem);
    int t = threadIdx.x, wid = t >> 5, lane = t & 31;
    int wm = wid & 3, wn = wid >> 2;
    int gid = lane >> 2, tig = lane & 3;
    int n0 = blockIdx.x * NT;
    int m0 = blockIdx.y * MT;

    float acc[2][8][4];
    #pragma unroll
    for (int mt = 0; mt < 2; ++mt)
        #pragma unroll
        for (int nt = 0; nt < 8; ++nt)
            #pragma unroll
            for (int e = 0; e < 4; ++e) acc[mt][nt][e] = 0.f;

    issue_stage(sb, 0, m0, n0, t, Ah, Al, Bh, Bl);
    CP_COMMIT();
    issue_stage(sb + STAGE_B, 1, m0, n0, t, Ah, Al, Bh, Bl);
    CP_COMMIT();

    for (int kt = 0; kt < NKT; ++kt) {
        if (kt == NKT - 1) { CP_WAIT0(); } else { CP_WAIT1(); }
        __syncthreads();

        uint32_t stage = sb + (kt & 1) * STAGE_B;
        uint32_t aBaseH = stage + 0 * ARR_B + (uint32_t)(wm * 32 + gid) * ROWB + tig * 4;
        uint32_t aBaseL = stage + 1 * ARR_B + (uint32_t)(wm * 32 + gid) * ROWB + tig * 4;
        uint32_t bBaseH = stage + 2 * ARR_B + (uint32_t)(wn * 64 + gid) * ROWB + tig * 4;
        uint32_t bBaseL = stage + 3 * ARR_B + (uint32_t)(wn * 64 + gid) * ROWB + tig * 4;

        #pragma unroll
        for (int kk = 0; kk < 2; ++kk) {
            uint32_t ko = kk * 32;
            uint32_t ah[2][4], al[2][4];
            #pragma unroll
            for (int mt = 0; mt < 2; ++mt) {
                uint32_t a = aBaseH + mt * (16 * ROWB) + ko;
                ah[mt][0] = lds32(a);
                ah[mt][1] = lds32(a + 8 * ROWB);
                ah[mt][2] = lds32(a + 16);
                ah[mt][3] = lds32(a + 8 * ROWB + 16);
                uint32_t b = aBaseL + mt * (16 * ROWB) + ko;
                al[mt][0] = lds32(b);
                al[mt][1] = lds32(b + 8 * ROWB);
                al[mt][2] = lds32(b + 16);
                al[mt][3] = lds32(b + 8 * ROWB + 16);
            }
            // process B fragments in two halves of 4 n-tiles (reg pressure).
            // TERM-MAJOR issue order: all 8 accumulators per term ->
            // reuse distance 8 independent MMAs covers HMMA latency.
            #pragma unroll
            for (int hlf = 0; hlf < 2; ++hlf) {
                uint32_t bh[4][2], bl[4][2];
                #pragma unroll
                for (int q = 0; q < 4; ++q) {
                    int nt = hlf * 4 + q;
                    uint32_t a = bBaseH + nt * (8 * ROWB) + ko;
                    bh[q][0] = lds32(a);
                    bh[q][1] = lds32(a + 16);
                    uint32_t b = bBaseL + nt * (8 * ROWB) + ko;
                    bl[q][0] = lds32(b);
                    bl[q][1] = lds32(b + 16);
                }
                // term 1: Ah * Bh
                #pragma unroll
                for (int mt = 0; mt < 2; ++mt)
                    #pragma unroll
                    for (int q = 0; q < 4; ++q)
                        MMA16816(acc[mt][hlf * 4 + q], ah[mt], bh[q]);
                // term 2: Ah * Bl
                #pragma unroll
                for (int mt = 0; mt < 2; ++mt)
                    #pragma unroll
                    for (int q = 0; q < 4; ++q)
                        MMA16816(acc[mt][hlf * 4 + q], ah[mt], bl[q]);
                // term 3: Al * Bh
                #pragma unroll
                for (int mt = 0; mt < 2; ++mt)
                    #pragma unroll
                    for (int q = 0; q < 4; ++q)
                        MMA16816(acc[mt][hlf * 4 + q], al[mt], bh[q]);
            }
        }
        __syncthreads();
        if (kt + 2 < NKT) {
            issue_stage(sb + (kt & 1) * STAGE_B, kt + 2, m0, n0, t, Ah, Al, Bh, Bl);
            CP_COMMIT();
        }
    }

    #pragma unroll
    for (int mt = 0; mt < 2; ++mt) {
        int r0 = m0 + wm * 32 + mt * 16 + gid;
        #pragma unroll
        for (int nt = 0; nt < 8; ++nt) {
            int c = n0 + wn * 64 + nt * 8 + 2 * tig;
            float2 v0 = make_float2(acc[mt][nt][0], acc[mt][nt][1]);
            float2 v1 = make_float2(acc[mt][nt][2], acc[mt][nt][3]);
            if (bias) {
                float b0 = bias[c], b1 = bias[c + 1];
                v0.x += b0; v0.y += b1; v1.x += b0; v1.y += b1;
            }
            *(float2*)(C + (size_t)r0 * 1024 + c) = v0;
            *(float2*)(C + (size_t)(r0 + 8) * 1024 + c) = v1;
        }
    }
}

// ================= rel key table =================
__global__ void rel_table_kernel(const float* __restrict__ W_rel,
                                 const float* __restrict__ b_rel)
{
    __shared__ float enc[64];
    int r = blockIdx.x;
    float p = (float)(128 - r);         // position i - j
    int t = threadIdx.x;
    if (t < 32) {
        float inv = powf(10000.0f, -(2.0f * (float)t) / 64.0f);
        float pe = p * inv;
        enc[t]      = sinf(pe);
        enc[t + 32] = cosf(pe);
    }
    __syncthreads();
    float acc = b_rel[t];
    #pragma unroll 8
    for (int k = 0; k < 64; ++k) acc += enc[k] * W_rel[k * 64 + t];
    g_R[r * 64 + t] = acc;
}

// ================= relvec v2 (register-blocked) =================
__global__ void __launch_bounds__(256)
relvec2_kernel(const float* __restrict__ rbias)
{
    __shared__ float QrT[64 * 68];   // [k][i]
    __shared__ float Rt[64 * 68];    // [k][d]

    int bh = blockIdx.x >> 4;        // 64 bh
    int b = bh >> 4, h = bh & 15;
    int i0 = (blockIdx.x & 15) * 64;
    int t = threadIdx.x;
    int ii = t >> 4, di = t & 15;

    #pragma unroll
    for (int p = 0; p < 4; ++p) {
        int idx = t + p * 256;
        int row = idx >> 4, sg = idx & 15;
        float4 v = *(const float4*)(g_q + (((size_t)(b * T_SEQ + i0 + row)) * NH + h) * HD + sg * 4);
        float4 rb4 = *(const float4*)(rbias + h * HD + sg * 4);
        QrT[(sg * 4 + 0) * 68 + row] = v.x + rb4.x;
        QrT[(sg * 4 + 1) * 68 + row] = v.y + rb4.y;
        QrT[(sg * 4 + 2) * 68 + row] = v.z + rb4.z;
        QrT[(sg * 4 + 3) * 68 + row] = v.w + rb4.w;
    }

    for (int dt = 0; dt < 5; ++dt) {
        int d0 = dt * 64;
        __syncthreads();
        #pragma unroll
        for (int p = 0; p < 4; ++p) {
            int idx = t + p * 256;
            int dl = idx >> 4, sg = idx & 15;
            int d = d0 + dl;
            float4 v = {0, 0, 0, 0};
            if (d < NDIAG) v = *(const float4*)(g_R + d * 64 + sg * 4);
            Rt[(sg * 4 + 0) * 68 + dl] = v.x;
            Rt[(sg * 4 + 1) * 68 + dl] = v.y;
            Rt[(sg * 4 + 2) * 68 + dl] = v.z;
            Rt[(sg * 4 + 3) * 68 + dl] = v.w;
        }
        __syncthreads();

        float acc[4][4];
        #pragma unroll
        for (int r = 0; r < 4; ++r)
            #pragma unroll
            for (int c = 0; c < 4; ++c) acc[r][c] = 0.f;

        #pragma unroll 4
        for (int k = 0; k < 64; ++k) {
            float4 qv = *(float4*)&QrT[k * 68 + ii * 4];
            float4 rv = *(float4*)&Rt[k * 68 + di * 4];
            float qa[4] = {qv.x, qv.y, qv.z, qv.w};
            float ra[4] = {rv.x, rv.y, rv.z, rv.w};
            #pragma unroll
            for (int r = 0; r < 4; ++r)
                #pragma unroll
                for (int c = 0; c < 4; ++c) acc[r][c] += qa[r] * ra[c];
        }

        if (d0 + di * 4 < NDIAG) {
            #pragma unroll
            for (int r = 0; r < 4; ++r) {
                size_t base = ((size_t)bh * T_SEQ + i0 + ii * 4 + r) * NDIAGP + d0 + di * 4;
                if (d0 + di * 4 + 3 < NDIAG) {
                    float4 o = {acc[r][0], acc[r][1], acc[r][2], acc[r][3]};
                    *(float4*)(g_relv + base) = o;
                } else {
                    #pragma unroll
                    for (int c = 0; c < 4; ++c)
                        if (d0 + di * 4 + c < NDIAG) g_relv[base + c] = acc[r][c];
                }
            }
        }
    }
}

// ================= banded flash attention v2 (register-blocked) =================
#define ATT_SMEM (4 * 64 * 68 * 4)   // QsT,KsT,Vs,Ss  = 69632 B

__global__ void __launch_bounds__(256, 1)
attn2_kernel(const float* __restrict__ cbias)
{
    float* QsT = (float*)dynsmem;          // [k][q] stride 68
    float* KsT = QsT + 64 * 68;            // [k][j]
    float* Vs  = KsT + 64 * 68;            // [j][d]
    float* Ss  = Vs  + 64 * 68;            // [q][j]

    int bh = blockIdx.x >> 4;
    int b = bh >> 4, h = bh & 15;
    int i0 = (blockIdx.x & 15) * 64;
    int t = threadIdx.x;
    int qi = t >> 4, ci = t & 15;

    #pragma unroll
    for (int p = 0; p < 4; ++p) {
        int idx = t + p * 256;
        int row = idx >> 4, sg = idx & 15;
        float4 v = *(const float4*)(g_q + (((size_t)(b * T_SEQ + i0 + row)) * NH + h) * HD + sg * 4);
        float4 cb4 = *(const float4*)(cbias + h * HD + sg * 4);
        QsT[(sg * 4 + 0) * 68 + row] = v.x + cb4.x;
        QsT[(sg * 4 + 1) * 68 + row] = v.y + cb4.y;
        QsT[(sg * 4 + 2) * 68 + row] = v.z + cb4.z;
        QsT[(sg * 4 + 3) * 68 + row] = v.w + cb4.w;
    }

    float m[4], l[4], O[4][4];
    #pragma unroll
    for (int r = 0; r < 4; ++r) {
        m[r] = -1e30f; l[r] = 0.f;
        #pragma unroll
        for (int c = 0; c < 4; ++c) O[r][c] = 0.f;
    }

    int jstart = (i0 - 128 > 0) ? (i0 - 128) : 0;    // multiple of 64
    int jendi  = i0 + 63 + 128;
    if (jendi > T_SEQ - 1) jendi = T_SEQ - 1;

    for (int j0 = jstart; j0 <= jendi; j0 += 64) {
        #pragma unroll
        for (int p = 0; p < 4; ++p) {
            int idx = t + p * 256;
            int jl = idx >> 4, sg = idx & 15;
            int j = j0 + jl;
            float4 kv = {0, 0, 0, 0}, vv = {0, 0, 0, 0};
            if (j < T_SEQ) {
                size_t base = (((size_t)(b * T_SEQ + j)) * NH + h) * HD + sg * 4;
                kv = *(const float4*)(g_k + base);
                vv = *(const float4*)(g_v + base);
            }
            KsT[(sg * 4 + 0) * 68 + jl] = kv.x;
            KsT[(sg * 4 + 1) * 68 + jl] = kv.y;
            KsT[(sg * 4 + 2) * 68 + jl] = kv.z;
            KsT[(sg * 4 + 3) * 68 + jl] = kv.w;
            *(float4*)&Vs[jl * 68 + sg * 4] = vv;
        }
        __syncthreads();

        float sv[4][4];
        #pragma unroll
        for (int r = 0; r < 4; ++r)
            #pragma unroll
            for (int c = 0; c < 4; ++c) sv[r][c] = 0.f;

        #pragma unroll 4
        for (int k = 0; k < 64; ++k) {
            float4 qv = *(float4*)&QsT[k * 68 + qi * 4];
            float4 kv = *(float4*)&KsT[k * 68 + ci * 4];
            float qa[4] = {qv.x, qv.y, qv.z, qv.w};
            float ka[4] = {kv.x, kv.y, kv.z, kv.w};
            #pragma unroll
            for (int r = 0; r < 4; ++r)
                #pragma unroll
                for (int c = 0; c < 4; ++c) sv[r][c] += qa[r] * ka[c];
        }

        #pragma unroll
        for (int r = 0; r < 4; ++r) {
            int i = i0 + qi * 4 + r;
            size_t rb = ((size_t)bh * T_SEQ + i) * NDIAGP + (128 - i + j0);
            #pragma unroll
            for (int c = 0; c < 4; ++c) {
                int j = j0 + ci * 4 + c;
                bool ok = (j < T_SEQ) && (j - i <= 128) && (i - j <= 128);
                sv[r][c] = ok ? (sv[r][c] + __ldg(g_relv + rb + ci * 4 + c)) * 0.03125f
                              : -1e30f;
            }
        }

        #pragma unroll
        for (int r = 0; r < 4; ++r) {
            float cm = fmaxf(fmaxf(sv[r][0], sv[r][1]), fmaxf(sv[r][2], sv[r][3]));
            cm = fmaxf(cm, __shfl_xor_sync(0xffffffffu, cm, 1));
            cm = fmaxf(cm, __shfl_xor_sync(0xffffffffu, cm, 2));
            cm = fmaxf(cm, __shfl_xor_sync(0xffffffffu, cm, 4));
            cm = fmaxf(cm, __shfl_xor_sync(0xffffffffu, cm, 8));
            float mn = fmaxf(m[r], cm);
            float al = __expf(m[r] - mn);
            m[r] = mn;
            float p0 = __expf(sv[r][0] - mn);
            float p1 = __expf(sv[r][1] - mn);
            float p2 = __expf(sv[r][2] - mn);
            float p3 = __expf(sv[r][3] - mn);
            float rs = p0 + p1 + p2 + p3;
            rs += __shfl_xor_sync(0xffffffffu, rs, 1);
            rs += __shfl_xor_sync(0xffffffffu, rs, 2);
            rs += __shfl_xor_sync(0xffffffffu, rs, 4);
            rs += __shfl_xor_sync(0xffffffffu, rs, 8);
            l[r] = l[r] * al + rs;
            float4 pp = {p0, p1, p2, p3};
            *(float4*)&Ss[(qi * 4 + r) * 68 + ci * 4] = pp;
            #pragma unroll
            for (int c = 0; c < 4; ++c) O[r][c] *= al;
        }
        __syncthreads();

        #pragma unroll 2
        for (int j = 0; j < 64; ++j) {
            float4 vv = *(float4*)&Vs[j * 68 + ci * 4];
            float va[4] = {vv.x, vv.y, vv.z, vv.w};
            #pragma unroll
            for (int r = 0; r < 4; ++r) {
                float p = Ss[(qi * 4 + r) * 68 + j];
                #pragma unroll
                for (int c = 0; c < 4; ++c) O[r][c] += p * va[c];
            }
        }
        __syncthreads();
    }

    #pragma unroll
    for (int r = 0; r < 4; ++r) {
        float linv = 1.0f / l[r];
        int i = i0 + qi * 4 + r;
        float4 o = {O[r][0] * linv, O[r][1] * linv, O[r][2] * linv, O[r][3] * linv};
        *(float4*)(g_att + ((size_t)(b * T_SEQ + i)) * HID + h * HD + ci * 4) = o;
    }
}

// ================= launch =================
extern "C" void kernel_launch(void* const* d_in, const int* in_sizes, int n_in,
                              void* d_out, int out_size)
{
    const float* x    = (const float*)d_in[0];
    const float* Wq   = (const float*)d_in[1];
    const float* Wk   = (const float*)d_in[2];
    const float* Wv   = (const float*)d_in[3];
    const float* cb   = (const float*)d_in[4];
    const float* rb   = (const float*)d_in[5];
    const float* Wrel = (const float*)d_in[6];
    const float* brel = (const float*)d_in[7];
    const float* Wo   = (const float*)d_in[8];
    const float* bo   = (const float*)d_in[9];
    float* out = (float*)d_out;

    void *pq, *pk, *pv, *patt, *pAh, *pAl, *pWTh, *pWTl;
    cudaGetSymbolAddress(&pq,   g_q);
    cudaGetSymbolAddress(&pk,   g_k);
    cudaGetSymbolAddress(&pv,   g_v);
    cudaGetSymbolAddress(&patt, g_att);
    cudaGetSymbolAddress(&pAh,  g_A_hi);
    cudaGetSymbolAddress(&pAl,  g_A_lo);
    cudaGetSymbolAddress(&pWTh, g_WT_hi);
    cudaGetSymbolAddress(&pWTl, g_WT_lo);
    __nv_bfloat16* Ah  = (__nv_bfloat16*)pAh;
    __nv_bfloat16* Al  = (__nv_bfloat16*)pAl;
    __nv_bfloat16* WTh = (__nv_bfloat16*)pWTh;
    __nv_bfloat16* WTl = (__nv_bfloat16*)pWTl;

    cudaFuncSetAttribute(gemm_bf16x3_kernel,
                         cudaFuncAttributeMaxDynamicSharedMemorySize, DYN_SMEM_GEMM);
    cudaFuncSetAttribute(attn2_kernel,
                         cudaFuncAttributeMaxDynamicSharedMemorySize, ATT_SMEM);

    dim3 tgrid3(32, 32, 3);
    dim3 tgrid(32, 32);
    dim3 qkv_grid(HID / NT, NROWS / MT, 3);   // (8, 32, 3)
    dim3 o_grid(HID / NT, NROWS / MT, 1);

    trans_split_qkv_kernel<<<tgrid3, 256>>>(Wq, Wk, Wv, WTh, WTl);                 // 1
    split_kernel<<<NROWS * HID / 1024, 256>>>(x, Ah, Al);                          // 2
    trans_split_kernel<<<tgrid, 256>>>(Wo, WTh + 3ull * HID * EMB, WTl + 3ull * HID * EMB); // 3
    gemm_bf16x3_kernel<<<qkv_grid, 256, DYN_SMEM_GEMM>>>(Ah, Al, WTh, WTl, nullptr,
                                                         (float*)pq, (float*)pk, (float*)pv); // 4 (profiled)
    rel_table_kernel<<<NDIAG, 64>>>(Wrel, brel);                                   // 5
    relvec2_kernel<<<BATCH * NH * (T_SEQ / 64), 256>>>(rb);                        // 6
    attn2_kernel<<<BATCH * NH * (T_SEQ / 64), 256, ATT_SMEM>>>(cb);                // 7
    split_kernel<<<NROWS * HID / 1024, 256>>>((const float*)patt, Ah, Al);         // 8
    gemm_bf16x3_kernel<<<o_grid, 256, DYN_SMEM_GEMM>>>(Ah, Al, WTh + 3ull * HID * EMB, WTl + 3ull * HID * EMB, bo,
                                                       out, out, out);             // 9
}

// round 13
// speedup vs baseline: 1.0524x; 1.0524x over previous
#include <cuda_runtime.h>
#include <cuda_bf16.h>
#include <math.h>
#include <stdint.h>

#define BATCH 4
#define T_SEQ 1024
#define EMB   1024
#define NH    16
#define HD    64
#define HID   1024
#define NROWS (BATCH * T_SEQ)   // 4096
#define NDIAG 257
#define NDIAGP 260              // padded stride (float4-aligned rows)

// ---------------- scratch ----------------
__device__ float g_q[NROWS * HID];
__device__ float g_k[NROWS * HID];
__device__ float g_v[NROWS * HID];
__device__ float g_att[NROWS * HID];
__device__ float g_R[NDIAG * HD];
__device__ float g_relv[(size_t)BATCH * NH * T_SEQ * NDIAGP];
// bf16-split operands
__device__ __nv_bfloat16 g_A_hi[NROWS * HID];
__device__ __nv_bfloat16 g_A_lo[NROWS * HID];
__device__ __nv_bfloat16 g_WT_hi[4 * HID * EMB];   // W^T slots: 0=q 1=k 2=v 3=o
__device__ __nv_bfloat16 g_WT_lo[4 * HID * EMB];

// ================= helpers =================
__device__ __forceinline__ uint32_t smem_u32(const void* p) {
    uint32_t a;
    asm("{ .reg .u64 t; cvta.to.shared.u64 t, %1; cvt.u32.u64 %0, t; }"
        : "=r"(a) : "l"(p));
    return a;
}
__device__ __forceinline__ void cp16(uint32_t s, const void* g) {
    asm volatile("cp.async.cg.shared.global [%0], [%1], 16;"
                 :: "r"(s), "l"(g) : "memory");
}
#define CP_COMMIT() asm volatile("cp.async.commit_group;" ::: "memory")
#define CP_WAIT1()  asm volatile("cp.async.wait_group 1;" ::: "memory")
#define CP_WAIT0()  asm volatile("cp.async.wait_group 0;" ::: "memory")

#define MMA16816(d, a, b) \
    asm volatile("mma.sync.aligned.m16n8k16.row.col.f32.bf16.bf16.f32 " \
        "{%0,%1,%2,%3}, {%4,%5,%6,%7}, {%8,%9}, {%0,%1,%2,%3};" \
        : "+f"((d)[0]), "+f"((d)[1]), "+f"((d)[2]), "+f"((d)[3]) \
        : "r"((a)[0]), "r"((a)[1]), "r"((a)[2]), "r"((a)[3]), \
          "r"((b)[0]), "r"((b)[1]))

#define LDM4(r, addr) \
    asm volatile("ldmatrix.sync.aligned.m8n8.x4.shared.b16 {%0,%1,%2,%3}, [%4];" \
        : "=r"((r)[0]), "=r"((r)[1]), "=r"((r)[2]), "=r"((r)[3]) : "r"(addr))

// ================= split prep kernels (fp32 -> bf16 hi/lo) =================
__global__ void __launch_bounds__(256)
split_kernel(const float* __restrict__ A, __nv_bfloat16* __restrict__ hi,
             __nv_bfloat16* __restrict__ lo)
{
    size_t i = ((size_t)blockIdx.x * 256 + threadIdx.x) * 4;
    float4 v = *(const float4*)(A + i);
    __nv_bfloat16 h0 = __float2bfloat16(v.x);
    __nv_bfloat16 h1 = __float2bfloat16(v.y);
    __nv_bfloat16 h2 = __float2bfloat16(v.z);
    __nv_bfloat16 h3 = __float2bfloat16(v.w);
    __nv_bfloat162 hp0; hp0.x = h0; hp0.y = h1;
    __nv_bfloat162 hp1; hp1.x = h2; hp1.y = h3;
    __nv_bfloat162 lp0, lp1;
    lp0.x = __float2bfloat16(v.x - __bfloat162float(h0));
    lp0.y = __float2bfloat16(v.y - __bfloat162float(h1));
    lp1.x = __float2bfloat16(v.z - __bfloat162float(h2));
    lp1.y = __float2bfloat16(v.w - __bfloat162float(h3));
    *(__nv_bfloat162*)(hi + i)     = hp0;
    *(__nv_bfloat162*)(hi + i + 2) = hp1;
    *(__nv_bfloat162*)(lo + i)     = lp0;
    *(__nv_bfloat162*)(lo + i + 2) = lp1;
}

// out[n][k] = W[k][n], split hi/lo bf16.  slot = blockIdx.z selects src/dst.
__global__ void __launch_bounds__(256)
trans_split_qkv_kernel(const float* __restrict__ Wq, const float* __restrict__ Wk,
                       const float* __restrict__ Wv,
                       __nv_bfloat16* __restrict__ oh, __nv_bfloat16* __restrict__ ol)
{
    __shared__ float tile[32][33];
    int slot = blockIdx.z;
    const float* W = (slot == 0) ? Wq : (slot == 1) ? Wk : Wv;
    size_t dofs = (size_t)slot * HID * EMB;
    int n0 = blockIdx.x * 32, k0 = blockIdx.y * 32;
    int tx = threadIdx.x & 31, ty = threadIdx.x >> 5;  // 32 x 8
    #pragma unroll
    for (int r = ty; r < 32; r += 8)
        tile[r][tx] = W[(size_t)(k0 + r) * HID + n0 + tx];
    __syncthreads();
    #pragma unroll
    for (int r = ty; r < 32; r += 8) {
        float v = tile[tx][r];             // W[k0+tx][n0+r]
        __nv_bfloat16 h = __float2bfloat16(v);
        oh[dofs + (size_t)(n0 + r) * EMB + k0 + tx] = h;
        ol[dofs + (size_t)(n0 + r) * EMB + k0 + tx] =
            __float2bfloat16(v - __bfloat162float(h));
    }
}

__global__ void __launch_bounds__(256)
trans_split_kernel(const float* __restrict__ W, __nv_bfloat16* __restrict__ oh,
                   __nv_bfloat16* __restrict__ ol)
{
    __shared__ float tile[32][33];
    int n0 = blockIdx.x * 32, k0 = blockIdx.y * 32;
    int tx = threadIdx.x & 31, ty = threadIdx.x >> 5;
    #pragma unroll
    for (int r = ty; r < 32; r += 8)
        tile[r][tx] = W[(size_t)(k0 + r) * HID + n0 + tx];
    __syncthreads();
    #pragma unroll
    for (int r = ty; r < 32; r += 8) {
        float v = tile[tx][r];
        __nv_bfloat16 h = __float2bfloat16(v);
        oh[(size_t)(n0 + r) * EMB + k0 + tx] = h;
        ol[(size_t)(n0 + r) * EMB + k0 + tx] =
            __float2bfloat16(v - __bfloat162float(h));
    }
}

// ================= bf16x3 mma.sync GEMM (occ=2, ldmatrix fragments) =================
#define MT 128
#define NT 128
#define KT 32
#define NKT (EMB / KT)      // 32
#define ROWB 80
#define ARR_B (128 * ROWB)
#define STAGE_B (4 * ARR_B)
#define DYN_SMEM_GEMM (2 * STAGE_B)   // 81920
#define AHI_OFF 0
#define ALO_OFF ARR_B
#define BHI_OFF (2 * ARR_B)
#define BLO_OFF (3 * ARR_B)

extern __shared__ char dynsmem[];

__device__ __forceinline__ void issue_stage(
    uint32_t stage, int kt, int m0, int n0, int t,
    const __nv_bfloat16* __restrict__ Ah, const __nv_bfloat16* __restrict__ Al,
    const __nv_bfloat16* __restrict__ Bh, const __nv_bfloat16* __restrict__ Bl)
{
    const __nv_bfloat16* gp[4] = {Ah, Al, Bh, Bl};
    #pragma unroll
    for (int arr = 0; arr < 4; ++arr) {
        int rbase = (arr < 2) ? m0 : n0;
        uint32_t soff = stage + arr * ARR_B;
        #pragma unroll
        for (int q = 0; q < 2; ++q) {
            int c = t + q * 256;
            int row = c >> 2, seg = c & 3;
            const char* src = (const char*)(gp[arr] + (size_t)(rbase + row) * EMB + kt * KT)
                              + seg * 16;
            cp16(soff + row * ROWB + seg * 16, src);
        }
    }
}

// blockIdx.z selects weight slot + output target (C0/C1/C2).
__global__ void __launch_bounds__(256, 2)
gemm_bf16x3_kernel(const __nv_bfloat16* __restrict__ Ah, const __nv_bfloat16* __restrict__ Al,
                   const __nv_bfloat16* __restrict__ BhBase, const __nv_bfloat16* __restrict__ BlBase,
                   const float* __restrict__ bias,
                   float* __restrict__ C0, float* __restrict__ C1, float* __restrict__ C2)
{
    int slot = blockIdx.z;
    const __nv_bfloat16* Bh = BhBase + (size_t)slot * HID * EMB;
    const __nv_bfloat16* Bl = BlBase + (size_t)slot * HID * EMB;
    float* C = (slot == 0) ? C0 : (slot == 1) ? C1 : C2;

    uint32_t sb = smem_u32(dynsmem);
    int t = threadIdx.x, wid = t >> 5, lane = t & 31;
    int wm = wid & 3, wn = wid >> 2;
    int gid = lane >> 2, tig = lane & 3;
    int n0 = blockIdx.x * NT;
    int m0 = blockIdx.y * MT;

    // ldmatrix per-lane address offsets (within stage).
    // A m16k16 x4: tile t = lane>>3; (t&1)->m-half, (t>>1)->k-half.
    int lt = lane >> 3, lr = lane & 7;
    uint32_t aLdmOff = (uint32_t)(wm * 32 + (lt & 1) * 8 + lr) * ROWB
                     + (uint32_t)((lt >> 1) * 16);
    // B pair-of-n8 x4: (t>>1)->nt-within-pair, (t&1)->k-half.
    uint32_t bLdmOff = (uint32_t)(wn * 64 + (lt >> 1) * 8 + lr) * ROWB
                     + (uint32_t)((lt & 1) * 16);

    float acc[2][8][4];
    #pragma unroll
    for (int mt = 0; mt < 2; ++mt)
        #pragma unroll
        for (int nt = 0; nt < 8; ++nt)
            #pragma unroll
            for (int e = 0; e < 4; ++e) acc[mt][nt][e] = 0.f;

    issue_stage(sb, 0, m0, n0, t, Ah, Al, Bh, Bl);
    CP_COMMIT();
    issue_stage(sb + STAGE_B, 1, m0, n0, t, Ah, Al, Bh, Bl);
    CP_COMMIT();

    for (int kt = 0; kt < NKT; ++kt) {
        if (kt == NKT - 1) { CP_WAIT0(); } else { CP_WAIT1(); }
        __syncthreads();

        uint32_t stage = sb + (kt & 1) * STAGE_B;

        #pragma unroll
        for (int kk = 0; kk < 2; ++kk) {
            uint32_t ko = kk * 32;   // 16 bf16 = 32 bytes
            uint32_t ah[2][4], al[2][4];
            #pragma unroll
            for (int mt = 0; mt < 2; ++mt) {
                LDM4(ah[mt], stage + AHI_OFF + aLdmOff + mt * (16 * ROWB) + ko);
                LDM4(al[mt], stage + ALO_OFF + aLdmOff + mt * (16 * ROWB) + ko);
            }
            #pragma unroll
            for (int hlf = 0; hlf < 2; ++hlf) {
                // B fragments for 4 n-tiles via 2 ldmatrix.x4 per hi/lo:
                // regs {b[nt0][0], b[nt0][1], b[nt1][0], b[nt1][1]}
                uint32_t bhf[2][4], blf[2][4];
                #pragma unroll
                for (int qp = 0; qp < 2; ++qp) {
                    uint32_t rowoff = (uint32_t)((hlf * 4 + qp * 2) * 8 * ROWB);
                    LDM4(bhf[qp], stage + BHI_OFF + bLdmOff + rowoff + ko);
                    LDM4(blf[qp], stage + BLO_OFF + bLdmOff + rowoff + ko);
                }
                // term 1: Ah * Bh
                #pragma unroll
                for (int mt = 0; mt < 2; ++mt)
                    #pragma unroll
                    for (int q = 0; q < 4; ++q)
                        MMA16816(acc[mt][hlf * 4 + q], ah[mt], &bhf[q >> 1][2 * (q & 1)]);
                // term 2: Ah * Bl
                #pragma unroll
                for (int mt = 0; mt < 2; ++mt)
                    #pragma unroll
                    for (int q = 0; q < 4; ++q)
                        MMA16816(acc[mt][hlf * 4 + q], ah[mt], &blf[q >> 1][2 * (q & 1)]);
                // term 3: Al * Bh
                #pragma unroll
                for (int mt = 0; mt < 2; ++mt)
                    #pragma unroll
                    for (int q = 0; q < 4; ++q)
                        MMA16816(acc[mt][hlf * 4 + q], al[mt], &bhf[q >> 1][2 * (q & 1)]);
            }
        }
        __syncthreads();
        if (kt + 2 < NKT) {
            issue_stage(sb + (kt & 1) * STAGE_B, kt + 2, m0, n0, t, Ah, Al, Bh, Bl);
            CP_COMMIT();
        }
    }

    #pragma unroll
    for (int mt = 0; mt < 2; ++mt) {
        int r0 = m0 + wm * 32 + mt * 16 + gid;
        #pragma unroll
        for (int nt = 0; nt < 8; ++nt) {
            int c = n0 + wn * 64 + nt * 8 + 2 * tig;
            float2 v0 = make_float2(acc[mt][nt][0], acc[mt][nt][1]);
            float2 v1 = make_float2(acc[mt][nt][2], acc[mt][nt][3]);
            if (bias) {
                float b0 = bias[c], b1 = bias[c + 1];
                v0.x += b0; v0.y += b1; v1.x += b0; v1.y += b1;
            }
            *(float2*)(C + (size_t)r0 * 1024 + c) = v0;
            *(float2*)(C + (size_t)(r0 + 8) * 1024 + c) = v1;
        }
    }
}

// ================= rel key table =================
__global__ void rel_table_kernel(const float* __restrict__ W_rel,
                                 const float* __restrict__ b_rel)
{
    __shared__ float enc[64];
    int r = blockIdx.x;
    float p = (float)(128 - r);         // position i - j
    int t = threadIdx.x;
    if (t < 32) {
        float inv = powf(10000.0f, -(2.0f * (float)t) / 64.0f);
        float pe = p * inv;
        enc[t]      = sinf(pe);
        enc[t + 32] = cosf(pe);
    }
    __syncthreads();
    float acc = b_rel[t];
    #pragma unroll 8
    for (int k = 0; k < 64; ++k) acc += enc[k] * W_rel[k * 64 + t];
    g_R[r * 64 + t] = acc;
}

// ================= relvec v2 (register-blocked) =================
__global__ void __launch_bounds__(256)
relvec2_kernel(const float* __restrict__ rbias)
{
    __shared__ float QrT[64 * 68];   // [k][i]
    __shared__ float Rt[64 * 68];    // [k][d]

    int bh = blockIdx.x >> 4;        // 64 bh
    int b = bh >> 4, h = bh & 15;
    int i0 = (blockIdx.x & 15) * 64;
    int t = threadIdx.x;
    int ii = t >> 4, di = t & 15;

    #pragma unroll
    for (int p = 0; p < 4; ++p) {
        int idx = t + p * 256;
        int row = idx >> 4, sg = idx & 15;
        float4 v = *(const float4*)(g_q + (((size_t)(b * T_SEQ + i0 + row)) * NH + h) * HD + sg * 4);
        float4 rb4 = *(const float4*)(rbias + h * HD + sg * 4);
        QrT[(sg * 4 + 0) * 68 + row] = v.x + rb4.x;
        QrT[(sg * 4 + 1) * 68 + row] = v.y + rb4.y;
        QrT[(sg * 4 + 2) * 68 + row] = v.z + rb4.z;
        QrT[(sg * 4 + 3) * 68 + row] = v.w + rb4.w;
    }

    for (int dt = 0; dt < 5; ++dt) {
        int d0 = dt * 64;
        __syncthreads();
        #pragma unroll
        for (int p = 0; p < 4; ++p) {
            int idx = t + p * 256;
            int dl = idx >> 4, sg = idx & 15;
            int d = d0 + dl;
            float4 v = {0, 0, 0, 0};
            if (d < NDIAG) v = *(const float4*)(g_R + d * 64 + sg * 4);
            Rt[(sg * 4 + 0) * 68 + dl] = v.x;
            Rt[(sg * 4 + 1) * 68 + dl] = v.y;
            Rt[(sg * 4 + 2) * 68 + dl] = v.z;
            Rt[(sg * 4 + 3) * 68 + dl] = v.w;
        }
        __syncthreads();

        float acc[4][4];
        #pragma unroll
        for (int r = 0; r < 4; ++r)
            #pragma unroll
            for (int c = 0; c < 4; ++c) acc[r][c] = 0.f;

        #pragma unroll 4
        for (int k = 0; k < 64; ++k) {
            float4 qv = *(float4*)&QrT[k * 68 + ii * 4];
            float4 rv = *(float4*)&Rt[k * 68 + di * 4];
            float qa[4] = {qv.x, qv.y, qv.z, qv.w};
            float ra[4] = {rv.x, rv.y, rv.z, rv.w};
            #pragma unroll
            for (int r = 0; r < 4; ++r)
                #pragma unroll
                for (int c = 0; c < 4; ++c) acc[r][c] += qa[r] * ra[c];
        }

        if (d0 + di * 4 < NDIAG) {
            #pragma unroll
            for (int r = 0; r < 4; ++r) {
                size_t base = ((size_t)bh * T_SEQ + i0 + ii * 4 + r) * NDIAGP + d0 + di * 4;
                if (d0 + di * 4 + 3 < NDIAG) {
                    float4 o = {acc[r][0], acc[r][1], acc[r][2], acc[r][3]};
                    *(float4*)(g_relv + base) = o;
                } else {
                    #pragma unroll
                    for (int c = 0; c < 4; ++c)
                        if (d0 + di * 4 + c < NDIAG) g_relv[base + c] = acc[r][c];
                }
            }
        }
    }
}

// ================= banded flash attention v2 (register-blocked) =================
#define ATT_SMEM (4 * 64 * 68 * 4)   // QsT,KsT,Vs,Ss  = 69632 B

__global__ void __launch_bounds__(256, 1)
attn2_kernel(const float* __restrict__ cbias)
{
    float* QsT = (float*)dynsmem;          // [k][q] stride 68
    float* KsT = QsT + 64 * 68;            // [k][j]
    float* Vs  = KsT + 64 * 68;            // [j][d]
    float* Ss  = Vs  + 64 * 68;            // [q][j]

    int bh = blockIdx.x >> 4;
    int b = bh >> 4, h = bh & 15;
    int i0 = (blockIdx.x & 15) * 64;
    int t = threadIdx.x;
    int qi = t >> 4, ci = t & 15;

    #pragma unroll
    for (int p = 0; p < 4; ++p) {
        int idx = t + p * 256;
        int row = idx >> 4, sg = idx & 15;
        float4 v = *(const float4*)(g_q + (((size_t)(b * T_SEQ + i0 + row)) * NH + h) * HD + sg * 4);
        float4 cb4 = *(const float4*)(cbias + h * HD + sg * 4);
        QsT[(sg * 4 + 0) * 68 + row] = v.x + cb4.x;
        QsT[(sg * 4 + 1) * 68 + row] = v.y + cb4.y;
        QsT[(sg * 4 + 2) * 68 + row] = v.z + cb4.z;
        QsT[(sg * 4 + 3) * 68 + row] = v.w + cb4.w;
    }

    float m[4], l[4], O[4][4];
    #pragma unroll
    for (int r = 0; r < 4; ++r) {
        m[r] = -1e30f; l[r] = 0.f;
        #pragma unroll
        for (int c = 0; c < 4; ++c) O[r][c] = 0.f;
    }

    int jstart = (i0 - 128 > 0) ? (i0 - 128) : 0;    // multiple of 64
    int jendi  = i0 + 63 + 128;
    if (jendi > T_SEQ - 1) jendi = T_SEQ - 1;

    for (int j0 = jstart; j0 <= jendi; j0 += 64) {
        #pragma unroll
        for (int p = 0; p < 4; ++p) {
            int idx = t + p * 256;
            int jl = idx >> 4, sg = idx & 15;
            int j = j0 + jl;
            float4 kv = {0, 0, 0, 0}, vv = {0, 0, 0, 0};
            if (j < T_SEQ) {
                size_t base = (((size_t)(b * T_SEQ + j)) * NH + h) * HD + sg * 4;
                kv = *(const float4*)(g_k + base);
                vv = *(const float4*)(g_v + base);
            }
            KsT[(sg * 4 + 0) * 68 + jl] = kv.x;
            KsT[(sg * 4 + 1) * 68 + jl] = kv.y;
            KsT[(sg * 4 + 2) * 68 + jl] = kv.z;
            KsT[(sg * 4 + 3) * 68 + jl] = kv.w;
            *(float4*)&Vs[jl * 68 + sg * 4] = vv;
        }
        __syncthreads();

        float sv[4][4];
        #pragma unroll
        for (int r = 0; r < 4; ++r)
            #pragma unroll
            for (int c = 0; c < 4; ++c) sv[r][c] = 0.f;

        #pragma unroll 4
        for (int k = 0; k < 64; ++k) {
            float4 qv = *(float4*)&QsT[k * 68 + qi * 4];
            float4 kv = *(float4*)&KsT[k * 68 + ci * 4];
            float qa[4] = {qv.x, qv.y, qv.z, qv.w};
            float ka[4] = {kv.x, kv.y, kv.z, kv.w};
            #pragma unroll
            for (int r = 0; r < 4; ++r)
                #pragma unroll
                for (int c = 0; c < 4; ++c) sv[r][c] += qa[r] * ka[c];
        }

        #pragma unroll
        for (int r = 0; r < 4; ++r) {
            int i = i0 + qi * 4 + r;
            size_t rb = ((size_t)bh * T_SEQ + i) * NDIAGP + (128 - i + j0);
            #pragma unroll
            for (int c = 0; c < 4; ++c) {
                int j = j0 + ci * 4 + c;
                bool ok = (j < T_SEQ) && (j - i <= 128) && (i - j <= 128);
                sv[r][c] = ok ? (sv[r][c] + __ldg(g_relv + rb + ci * 4 + c)) * 0.03125f
                              : -1e30f;
            }
        }

        #pragma unroll
        for (int r = 0; r < 4; ++r) {
            float cm = fmaxf(fmaxf(sv[r][0], sv[r][1]), fmaxf(sv[r][2], sv[r][3]));
            cm = fmaxf(cm, __shfl_xor_sync(0xffffffffu, cm, 1));
            cm = fmaxf(cm, __shfl_xor_sync(0xffffffffu, cm, 2));
            cm = fmaxf(cm, __shfl_xor_sync(0xffffffffu, cm, 4));
            cm = fmaxf(cm, __shfl_xor_sync(0xffffffffu, cm, 8));
            float mn = fmaxf(m[r], cm);
            float al = __expf(m[r] - mn);
            m[r] = mn;
            float p0 = __expf(sv[r][0] - mn);
            float p1 = __expf(sv[r][1] - mn);
            float p2 = __expf(sv[r][2] - mn);
            float p3 = __expf(sv[r][3] - mn);
            float rs = p0 + p1 + p2 + p3;
            rs += __shfl_xor_sync(0xffffffffu, rs, 1);
            rs += __shfl_xor_sync(0xffffffffu, rs, 2);
            rs += __shfl_xor_sync(0xffffffffu, rs, 4);
            rs += __shfl_xor_sync(0xffffffffu, rs, 8);
            l[r] = l[r] * al + rs;
            float4 pp = {p0, p1, p2, p3};
            *(float4*)&Ss[(qi * 4 + r) * 68 + ci * 4] = pp;
            #pragma unroll
            for (int c = 0; c < 4; ++c) O[r][c] *= al;
        }
        __syncthreads();

        #pragma unroll 2
        for (int j = 0; j < 64; ++j) {
            float4 vv = *(float4*)&Vs[j * 68 + ci * 4];
            float va[4] = {vv.x, vv.y, vv.z, vv.w};
            #pragma unroll
            for (int r = 0; r < 4; ++r) {
                float p = Ss[(qi * 4 + r) * 68 + j];
                #pragma unroll
                for (int c = 0; c < 4; ++c) O[r][c] += p * va[c];
            }
        }
        __syncthreads();
    }

    #pragma unroll
    for (int r = 0; r < 4; ++r) {
        float linv = 1.0f / l[r];
        int i = i0 + qi * 4 + r;
        float4 o = {O[r][0] * linv, O[r][1] * linv, O[r][2] * linv, O[r][3] * linv};
        *(float4*)(g_att + ((size_t)(b * T_SEQ + i)) * HID + h * HD + ci * 4) = o;
    }
}

// ================= launch =================
extern "C" void kernel_launch(void* const* d_in, const int* in_sizes, int n_in,
                              void* d_out, int out_size)
{
    const float* x    = (const float*)d_in[0];
    const float* Wq   = (const float*)d_in[1];
    const float* Wk   = (const float*)d_in[2];
    const float* Wv   = (const float*)d_in[3];
    const float* cb   = (const float*)d_in[4];
    const float* rb   = (const float*)d_in[5];
    const float* Wrel = (const float*)d_in[6];
    const float* brel = (const float*)d_in[7];
    const float* Wo   = (const float*)d_in[8];
    const float* bo   = (const float*)d_in[9];
    float* out = (float*)d_out;

    void *pq, *pk, *pv, *patt, *pAh, *pAl, *pWTh, *pWTl;
    cudaGetSymbolAddress(&pq,   g_q);
    cudaGetSymbolAddress(&pk,   g_k);
    cudaGetSymbolAddress(&pv,   g_v);
    cudaGetSymbolAddress(&patt, g_att);
    cudaGetSymbolAddress(&pAh,  g_A_hi);
    cudaGetSymbolAddress(&pAl,  g_A_lo);
    cudaGetSymbolAddress(&pWTh, g_WT_hi);
    cudaGetSymbolAddress(&pWTl, g_WT_lo);
    __nv_bfloat16* Ah  = (__nv_bfloat16*)pAh;
    __nv_bfloat16* Al  = (__nv_bfloat16*)pAl;
    __nv_bfloat16* WTh = (__nv_bfloat16*)pWTh;
    __nv_bfloat16* WTl = (__nv_bfloat16*)pWTl;

    cudaFuncSetAttribute(gemm_bf16x3_kernel,
                         cudaFuncAttributeMaxDynamicSharedMemorySize, DYN_SMEM_GEMM);
    cudaFuncSetAttribute(attn2_kernel,
                         cudaFuncAttributeMaxDynamicSharedMemorySize, ATT_SMEM);

    dim3 tgrid3(32, 32, 3);
    dim3 tgrid(32, 32);
    dim3 qkv_grid(HID / NT, NROWS / MT, 3);   // (8, 32, 3)
    dim3 o_grid(HID / NT, NROWS / MT, 1);

    trans_split_qkv_kernel<<<tgrid3, 256>>>(Wq, Wk, Wv, WTh, WTl);                 // 1
    split_kernel<<<NROWS * HID / 1024, 256>>>(x, Ah, Al);                          // 2
    trans_split_kernel<<<tgrid, 256>>>(Wo, WTh + 3ull * HID * EMB, WTl + 3ull * HID * EMB); // 3
    gemm_bf16x3_kernel<<<qkv_grid, 256, DYN_SMEM_GEMM>>>(Ah, Al, WTh, WTl, nullptr,
                                                         (float*)pq, (float*)pk, (float*)pv); // 4 (profiled)
    rel_table_kernel<<<NDIAG, 64>>>(Wrel, brel);                                   // 5
    relvec2_kernel<<<BATCH * NH * (T_SEQ / 64), 256>>>(rb);                        // 6
    attn2_kernel<<<BATCH * NH * (T_SEQ / 64), 256, ATT_SMEM>>>(cb);                // 7
    split_kernel<<<NROWS * HID / 1024, 256>>>((const float*)patt, Ah, Al);         // 8
    gemm_bf16x3_kernel<<<o_grid, 256, DYN_SMEM_GEMM>>>(Ah, Al, WTh + 3ull * HID * EMB, WTl + 3ull * HID * EMB, bo,
                                                       out, out, out);             // 9
}